// round 12
// baseline (speedup 1.0000x reference)
#include <cuda_runtime.h>
#include <cuda_bf16.h>
#include <stdint.h>
#include <math.h>

#define NN 65536
#define EE 1048576
#define NEG 0.2f
#define EPSV 1e-16f

// ---------------- scratch (device globals: allocation-free) ----------------
__device__ int   g_is64;
__device__ int   g_src[EE];
__device__ int   g_dst[EE];
__device__ int   g_deg[NN];
__device__ int   g_off[NN + 1];
__device__ int   g_cur[NN];
__device__ int   g_csr[EE];
__device__ float g_h1[NN * 128];
__device__ float g_as1[NN * 4];
__device__ float g_ad1[NN * 4];
__device__ float g_out1[NN * 128];
__device__ float g_h2[NN * 64];
__device__ float g_as2[NN];
__device__ float g_ad2[NN];

__device__ __forceinline__ float lrelu(float a) { return a > 0.f ? a : NEG * a; }
__device__ __forceinline__ float sigm(float x) { return 1.f / (1.f + __expf(-x)); }
__device__ __forceinline__ uint32_t pack_bf2(__nv_bfloat16 a, __nv_bfloat16 b) {
    return ((uint32_t)__bfloat16_as_ushort(b) << 16) | (uint32_t)__bfloat16_as_ushort(a);
}
__device__ __forceinline__ void mma16816(float* c, const uint32_t* a, uint32_t b0, uint32_t b1) {
    asm volatile(
        "mma.sync.aligned.m16n8k16.row.col.f32.bf16.bf16.f32 "
        "{%0,%1,%2,%3}, {%4,%5,%6,%7}, {%8,%9}, {%0,%1,%2,%3};"
        : "+f"(c[0]), "+f"(c[1]), "+f"(c[2]), "+f"(c[3])
        : "r"(a[0]), "r"(a[1]), "r"(a[2]), "r"(a[3]), "r"(b0), "r"(b1));
}

// ---------------- preprocessing ----------------
__global__ void k_zero_detect(const unsigned int* __restrict__ ei) {
    int i = blockIdx.x * blockDim.x + threadIdx.x;
    for (int j = i; j < NN; j += gridDim.x * blockDim.x) g_deg[j] = 0;
    if (blockIdx.x == 0 && threadIdx.x < 32) {
        int lane = threadIdx.x;
        unsigned int nz = 0;
#pragma unroll
        for (int k = 0; k < 4; k++) nz |= ei[2 * (lane * 4 + k) + 1];
        unsigned int any = __ballot_sync(0xffffffffu, nz != 0u);
        if (lane == 0) g_is64 = (any == 0u) ? 1 : 0;
    }
}

__global__ void k_convert(const void* __restrict__ ei) {
    int base = blockIdx.x * 1024 + threadIdx.x;
    int is64 = g_is64;
#pragma unroll
    for (int j = 0; j < 4; j++) {
        int e = base + j * 256;
        int s, d;
        if (is64) {
            const long long* p = (const long long*)ei;
            s = (int)p[e];
            d = (int)p[EE + e];
        } else {
            const int* p = (const int*)ei;
            s = p[e];
            d = p[EE + e];
        }
        g_src[e] = s;
        g_dst[e] = d;
        atomicAdd(&g_deg[d], 1);
    }
}

__global__ void __launch_bounds__(1024) k_scan() {
    __shared__ int part[1024];
    int tid = threadIdx.x;
    const int per = NN / 1024;
    int base = tid * per;
    int s = 0;
    for (int i = 0; i < per; i++) s += g_deg[base + i];
    part[tid] = s;
    __syncthreads();
    for (int off = 1; off < 1024; off <<= 1) {
        int v = (tid >= off) ? part[tid - off] : 0;
        __syncthreads();
        part[tid] += v;
        __syncthreads();
    }
    int run = (tid == 0) ? 0 : part[tid - 1];
    for (int i = 0; i < per; i++) {
        g_off[base + i] = run;
        g_cur[base + i] = run;
        run += g_deg[base + i];
    }
    if (tid == 1023) g_off[NN] = part[1023];
}

__global__ void k_csr() {
    int base = blockIdx.x * 1024 + threadIdx.x;
#pragma unroll
    for (int j = 0; j < 4; j++) {
        int e = base + j * 256;
        int pos = atomicAdd(&g_cur[g_dst[e]], 1);
        g_csr[pos] = g_src[e];
    }
}

// ---------------- fused HMMA GEMM + attention dots ----------------
template <int NB, int HEADS_T, int HC>
__global__ void __launch_bounds__(256, 2) k_mma(
    const float* __restrict__ A, const float* __restrict__ Wsrc,
    const float* __restrict__ ats, const float* __restrict__ atd,
    float* __restrict__ Hout, float* __restrict__ as_out, float* __restrict__ ad_out) {
    constexpr int PITCH = 72;
    constexpr int BPW = (NB == 128) ? 136 : 72;
    constexpr int NT = NB / 8;
    extern __shared__ __align__(16) char smem[];
    __nv_bfloat16* Ah = (__nv_bfloat16*)smem;
    __nv_bfloat16* Al = Ah + 128 * PITCH;
    uint32_t* BPh = (uint32_t*)(Al + 128 * PITCH);
    uint32_t* BPl = BPh + 32 * BPW;
    float* s_as = (float*)(BPl + 32 * BPW);
    float* s_ad = s_as + NB;

    int t = threadIdx.x, w = t >> 5, lane = t & 31;
    int gid = lane >> 2, tid4 = lane & 3;
    int row0 = blockIdx.x * 128;
    int wr = w * 16;
    int r1 = wr + gid, r2 = r1 + 8;

    for (int idx = t; idx < NB; idx += 256) {
        s_as[idx] = ats[idx];
        s_ad[idx] = atd[idx];
    }

    float acc[NT][4];
#pragma unroll
    for (int nt = 0; nt < NT; nt++) {
        acc[nt][0] = 0.f; acc[nt][1] = 0.f; acc[nt][2] = 0.f; acc[nt][3] = 0.f;
    }

#pragma unroll
    for (int kc = 0; kc < 2; kc++) {
        if (kc) __syncthreads();
#pragma unroll
        for (int i = 0; i < 8; i++) {
            int idx = i * 256 + t;
            int r = idx >> 4, c4 = idx & 15;
            float4 v = *(const float4*)&A[(size_t)(row0 + r) * 128 + kc * 64 + c4 * 4];
            __nv_bfloat16 hx = __float2bfloat16(v.x), hy = __float2bfloat16(v.y);
            __nv_bfloat16 hz = __float2bfloat16(v.z), hw = __float2bfloat16(v.w);
            __nv_bfloat16 lx = __float2bfloat16(v.x - __bfloat162float(hx));
            __nv_bfloat16 ly = __float2bfloat16(v.y - __bfloat162float(hy));
            __nv_bfloat16 lz = __float2bfloat16(v.z - __bfloat162float(hz));
            __nv_bfloat16 lw = __float2bfloat16(v.w - __bfloat162float(hw));
            int o = r * PITCH + c4 * 4;
            *(uint2*)&Ah[o] = make_uint2(pack_bf2(hx, hy), pack_bf2(hz, hw));
            *(uint2*)&Al[o] = make_uint2(pack_bf2(lx, ly), pack_bf2(lz, lw));
        }
#pragma unroll
        for (int idx = t; idx < 32 * (NB / 4); idx += 256) {
            int k2 = idx / (NB / 4), n4 = idx % (NB / 4);
            const float* wr0 = &Wsrc[(size_t)(kc * 64 + 2 * k2) * NB + n4 * 4];
            float4 w0 = *(const float4*)wr0;
            float4 w1 = *(const float4*)(wr0 + NB);
            float f0[4] = {w0.x, w0.y, w0.z, w0.w};
            float f1[4] = {w1.x, w1.y, w1.z, w1.w};
            uint32_t ph[4], pl[4];
#pragma unroll
            for (int j = 0; j < 4; j++) {
                __nv_bfloat16 h0 = __float2bfloat16(f0[j]);
                __nv_bfloat16 h1 = __float2bfloat16(f1[j]);
                __nv_bfloat16 l0 = __float2bfloat16(f0[j] - __bfloat162float(h0));
                __nv_bfloat16 l1 = __float2bfloat16(f1[j] - __bfloat162float(h1));
                ph[j] = pack_bf2(h0, h1);
                pl[j] = pack_bf2(l0, l1);
            }
            *(uint4*)&BPh[k2 * BPW + n4 * 4] = make_uint4(ph[0], ph[1], ph[2], ph[3]);
            *(uint4*)&BPl[k2 * BPW + n4 * 4] = make_uint4(pl[0], pl[1], pl[2], pl[3]);
        }
        __syncthreads();

#pragma unroll
        for (int kt = 0; kt < 4; kt++) {
            int k0 = kt * 16 + tid4 * 2;
            int p0 = kt * 8 + tid4;
            uint32_t ah[4], al[4];
            ah[0] = *(const uint32_t*)&Ah[r1 * PITCH + k0];
            ah[1] = *(const uint32_t*)&Ah[r2 * PITCH + k0];
            ah[2] = *(const uint32_t*)&Ah[r1 * PITCH + k0 + 8];
            ah[3] = *(const uint32_t*)&Ah[r2 * PITCH + k0 + 8];
            al[0] = *(const uint32_t*)&Al[r1 * PITCH + k0];
            al[1] = *(const uint32_t*)&Al[r2 * PITCH + k0];
            al[2] = *(const uint32_t*)&Al[r1 * PITCH + k0 + 8];
            al[3] = *(const uint32_t*)&Al[r2 * PITCH + k0 + 8];
#pragma unroll
            for (int nt = 0; nt < NT; nt++) {
                int nr = nt * 8 + gid;
                uint32_t bh0 = BPh[p0 * BPW + nr];
                uint32_t bh1 = BPh[(p0 + 4) * BPW + nr];
                uint32_t bl0 = BPl[p0 * BPW + nr];
                uint32_t bl1 = BPl[(p0 + 4) * BPW + nr];
                mma16816(acc[nt], ah, bh0, bh1);
                mma16816(acc[nt], ah, bl0, bl1);
                mma16816(acc[nt], al, bh0, bh1);
            }
        }
    }

    float accs[2][HEADS_T], accd[2][HEADS_T];
#pragma unroll
    for (int i = 0; i < 2; i++)
#pragma unroll
        for (int h = 0; h < HEADS_T; h++) { accs[i][h] = 0.f; accd[i][h] = 0.f; }

    int gr1 = row0 + r1, gr2 = row0 + r2;
#pragma unroll
    for (int nt = 0; nt < NT; nt++) {
        const int hidx = (nt * 8) / HC;
        int c0 = nt * 8 + tid4 * 2;
        float as0 = s_as[c0], as1 = s_as[c0 + 1];
        float ad0 = s_ad[c0], ad1 = s_ad[c0 + 1];
        accs[0][hidx] += acc[nt][0] * as0 + acc[nt][1] * as1;
        accd[0][hidx] += acc[nt][0] * ad0 + acc[nt][1] * ad1;
        accs[1][hidx] += acc[nt][2] * as0 + acc[nt][3] * as1;
        accd[1][hidx] += acc[nt][2] * ad0 + acc[nt][3] * ad1;
        *(float2*)&Hout[(size_t)gr1 * NB + c0] = make_float2(acc[nt][0], acc[nt][1]);
        *(float2*)&Hout[(size_t)gr2 * NB + c0] = make_float2(acc[nt][2], acc[nt][3]);
    }
#pragma unroll
    for (int off = 1; off <= 2; off <<= 1) {
#pragma unroll
        for (int i = 0; i < 2; i++)
#pragma unroll
            for (int h = 0; h < HEADS_T; h++) {
                accs[i][h] += __shfl_xor_sync(0xffffffffu, accs[i][h], off);
                accd[i][h] += __shfl_xor_sync(0xffffffffu, accd[i][h], off);
            }
    }
    if (tid4 == 0) {
#pragma unroll
        for (int h = 0; h < HEADS_T; h++) {
            as_out[(size_t)gr1 * HEADS_T + h] = accs[0][h];
            ad_out[(size_t)gr1 * HEADS_T + h] = accd[0][h];
            as_out[(size_t)gr2 * HEADS_T + h] = accs[1][h];
            ad_out[(size_t)gr2 * HEADS_T + h] = accd[1][h];
        }
    }
}

// ---------------- layer-1 aggregation: lane-owns-float4, 4x unrolled MLP ----------------
__global__ void k_agg1(const float* __restrict__ h, const float* __restrict__ b,
                       float* __restrict__ out) {
    int n = (blockIdx.x * blockDim.x + threadIdx.x) >> 5;
    int lane = threadIdx.x & 31;
    if (n >= NN) return;
    int hsel = lane >> 3;
    int beg = g_off[n], end = g_off[n + 1];
    float4 ad = *(const float4*)&g_ad1[n * 4];

    float4 acc = make_float4(0.f, 0.f, 0.f, 0.f);
    float d0 = 0.f, d1 = 0.f, d2 = 0.f, d3 = 0.f;

    for (int e0 = beg; e0 < end; e0 += 32) {
        int cnt = min(32, end - e0);
        int s = 0;
        float w0 = 0.f, w1 = 0.f, w2 = 0.f, w3 = 0.f;
        if (lane < cnt) {
            s = g_csr[e0 + lane];
            float4 as = *(const float4*)&g_as1[s * 4];
            w0 = __expf(lrelu(as.x + ad.x));
            w1 = __expf(lrelu(as.y + ad.y));
            w2 = __expf(lrelu(as.z + ad.z));
            w3 = __expf(lrelu(as.w + ad.w));
            d0 += w0; d1 += w1; d2 += w2; d3 += w3;
        }
        int j = 0;
        for (; j + 4 <= cnt; j += 4) {
            int sj[4];
            float uq[4];
            float4 v[4];
#pragma unroll
            for (int q = 0; q < 4; q++) {
                int ln = j + q;
                sj[q] = __shfl_sync(0xffffffffu, s, ln);
                float u0 = __shfl_sync(0xffffffffu, w0, ln);
                float u1 = __shfl_sync(0xffffffffu, w1, ln);
                float u2 = __shfl_sync(0xffffffffu, w2, ln);
                float u3 = __shfl_sync(0xffffffffu, w3, ln);
                uq[q] = (hsel < 2) ? (hsel == 0 ? u0 : u1) : (hsel == 2 ? u2 : u3);
            }
#pragma unroll
            for (int q = 0; q < 4; q++)
                v[q] = *(const float4*)&h[(size_t)sj[q] * 128 + lane * 4];
#pragma unroll
            for (int q = 0; q < 4; q++) {
                acc.x += uq[q] * v[q].x;
                acc.y += uq[q] * v[q].y;
                acc.z += uq[q] * v[q].z;
                acc.w += uq[q] * v[q].w;
            }
        }
        for (; j < cnt; j++) {
            int sj = __shfl_sync(0xffffffffu, s, j);
            float u0 = __shfl_sync(0xffffffffu, w0, j);
            float u1 = __shfl_sync(0xffffffffu, w1, j);
            float u2 = __shfl_sync(0xffffffffu, w2, j);
            float u3 = __shfl_sync(0xffffffffu, w3, j);
            float uq = (hsel < 2) ? (hsel == 0 ? u0 : u1) : (hsel == 2 ? u2 : u3);
            float4 v = *(const float4*)&h[(size_t)sj * 128 + lane * 4];
            acc.x += uq * v.x;
            acc.y += uq * v.y;
            acc.z += uq * v.z;
            acc.w += uq * v.w;
        }
    }
#pragma unroll
    for (int off = 16; off > 0; off >>= 1) {
        d0 += __shfl_xor_sync(0xffffffffu, d0, off);
        d1 += __shfl_xor_sync(0xffffffffu, d1, off);
        d2 += __shfl_xor_sync(0xffffffffu, d2, off);
        d3 += __shfl_xor_sync(0xffffffffu, d3, off);
    }
    float dsel = (hsel < 2) ? (hsel == 0 ? d0 : d1) : (hsel == 2 ? d2 : d3);
    float r = 1.f / (dsel + EPSV);
    float4 bv = *(const float4*)&b[lane * 4];
    float4 o;
    o.x = sigm(acc.x * r + bv.x);
    o.y = sigm(acc.y * r + bv.y);
    o.z = sigm(acc.z * r + bv.z);
    o.w = sigm(acc.w * r + bv.w);
    *(float4*)&out[(size_t)n * 128 + lane * 4] = o;
}

// ---------------- layer-2 aggregation: lane-owns-float2, 4x unrolled ----------------
__global__ void k_agg2(const float* __restrict__ h, const float* __restrict__ b,
                       float* __restrict__ out) {
    int n = (blockIdx.x * blockDim.x + threadIdx.x) >> 5;
    int lane = threadIdx.x & 31;
    if (n >= NN) return;
    int beg = g_off[n], end = g_off[n + 1];
    float ad = g_ad2[n];

    float2 acc = make_float2(0.f, 0.f);
    float d = 0.f;
    for (int e0 = beg; e0 < end; e0 += 32) {
        int cnt = min(32, end - e0);
        int s = 0;
        float w = 0.f;
        if (lane < cnt) {
            s = g_csr[e0 + lane];
            w = __expf(lrelu(g_as2[s] + ad));
            d += w;
        }
        int j = 0;
        for (; j + 4 <= cnt; j += 4) {
            int sj[4];
            float u[4];
            float2 v[4];
#pragma unroll
            for (int q = 0; q < 4; q++) {
                sj[q] = __shfl_sync(0xffffffffu, s, j + q);
                u[q] = __shfl_sync(0xffffffffu, w, j + q);
            }
#pragma unroll
            for (int q = 0; q < 4; q++)
                v[q] = *(const float2*)&h[(size_t)sj[q] * 64 + lane * 2];
#pragma unroll
            for (int q = 0; q < 4; q++) {
                acc.x += u[q] * v[q].x;
                acc.y += u[q] * v[q].y;
            }
        }
        for (; j < cnt; j++) {
            int sj = __shfl_sync(0xffffffffu, s, j);
            float u = __shfl_sync(0xffffffffu, w, j);
            float2 v = *(const float2*)&h[(size_t)sj * 64 + lane * 2];
            acc.x += u * v.x;
            acc.y += u * v.y;
        }
    }
#pragma unroll
    for (int off = 16; off > 0; off >>= 1)
        d += __shfl_xor_sync(0xffffffffu, d, off);
    float r = 1.f / (d + EPSV);
    float2 bv = *(const float2*)&b[lane * 2];
    float2 o;
    o.x = sigm(acc.x * r + bv.x);
    o.y = sigm(acc.y * r + bv.y);
    *(float2*)&out[(size_t)n * 64 + lane * 2] = o;
}

// ---------------- launch ----------------
extern "C" void kernel_launch(void* const* d_in, const int* in_sizes, int n_in,
                              void* d_out, int out_size) {
    const float* x     = (const float*)d_in[0];
    const void*  ei    = d_in[1];
    const float* W1    = (const float*)d_in[2];
    const float* at_s1 = (const float*)d_in[3];
    const float* at_d1 = (const float*)d_in[4];
    const float* b1    = (const float*)d_in[5];
    const float* W2    = (const float*)d_in[6];
    const float* at_s2 = (const float*)d_in[7];
    const float* at_d2 = (const float*)d_in[8];
    const float* b2    = (const float*)d_in[9];
    float* out = (float*)d_out;

    float *h1p, *out1p, *h2p, *as1p, *ad1p, *as2p, *ad2p;
    cudaGetSymbolAddress((void**)&h1p, g_h1);
    cudaGetSymbolAddress((void**)&out1p, g_out1);
    cudaGetSymbolAddress((void**)&h2p, g_h2);
    cudaGetSymbolAddress((void**)&as1p, g_as1);
    cudaGetSymbolAddress((void**)&ad1p, g_ad1);
    cudaGetSymbolAddress((void**)&as2p, g_as2);
    cudaGetSymbolAddress((void**)&ad2p, g_ad2);

    const int SM1 = 4 * 128 * 72 * 2 / 2 * 2 + 2 * 32 * 136 * 4 + 2 * 128 * 4;  // 72704
    const int SM2 = 2 * 128 * 72 * 2 + 2 * 32 * 72 * 4 + 2 * 64 * 4;            // 55808
    cudaFuncSetAttribute(k_mma<128, 4, 32>, cudaFuncAttributeMaxDynamicSharedMemorySize, SM1);
    cudaFuncSetAttribute(k_mma<64, 1, 64>, cudaFuncAttributeMaxDynamicSharedMemorySize, SM2);

    // Base sequence (identical to the 355us kernel; mma1 at ncu capture index 3)
    k_zero_detect<<<256, 256>>>((const unsigned int*)ei);               // 0
    k_convert<<<EE / 1024, 256>>>(ei);                                  // 1
    k_scan<<<1, 1024>>>();                                              // 2
    k_mma<128, 4, 32><<<NN / 128, 256, SM1>>>(x, W1, at_s1, at_d1,      // 3
                                              h1p, as1p, ad1p);
    k_csr<<<EE / 1024, 256>>>();                                        // 4
    k_agg1<<<NN / 8, 256>>>(h1p, b1, out1p);                            // 5
    k_mma<64, 1, 64><<<NN / 128, 256, SM2>>>(out1p, W2, at_s2, at_d2,   // 6
                                             h2p, as2p, ad2p);
    k_agg2<<<NN / 8, 256>>>(h2p, b2, out);                              // 7

    // DIAGNOSTIC duplicates (idempotent: same inputs -> same outputs rewritten).
    // total_dur - 355us  ==  agg1 + mma2 + agg2  (the three unmeasured kernels)
    k_agg1<<<NN / 8, 256>>>(h1p, b1, out1p);                            // 8
    k_mma<64, 1, 64><<<NN / 128, 256, SM2>>>(out1p, W2, at_s2, at_d2,   // 9
                                             h2p, as2p, ad2p);
    k_agg2<<<NN / 8, 256>>>(h2p, b2, out);                              // 10
}

// round 13
// speedup vs baseline: 2.5562x; 2.5562x over previous
#include <cuda_runtime.h>
#include <cuda_bf16.h>
#include <stdint.h>
#include <math.h>

#define NN 65536
#define EE 1048576
#define NEG 0.2f
#define EPSV 1e-16f

// ---------------- scratch (device globals: allocation-free) ----------------
__device__ int   g_is64;
__device__ int   g_src[EE];
__device__ int   g_dst[EE];
__device__ int   g_deg[NN];
__device__ int   g_excl[NN];
__device__ int   g_bsum[64];
__device__ int   g_off[NN + 1];
__device__ int   g_cur[NN];
__device__ int   g_csr[EE];
__device__ float g_h1[NN * 128];
__device__ float g_as1[NN * 4];
__device__ float g_ad1[NN * 4];
__device__ float g_out1[NN * 128];
__device__ float g_h2[NN * 64];
__device__ float g_as2[NN];
__device__ float g_ad2[NN];

__device__ __forceinline__ float lrelu(float a) { return a > 0.f ? a : NEG * a; }
__device__ __forceinline__ float sigm(float x) { return 1.f / (1.f + __expf(-x)); }
__device__ __forceinline__ uint32_t pack_bf2(__nv_bfloat16 a, __nv_bfloat16 b) {
    return ((uint32_t)__bfloat16_as_ushort(b) << 16) | (uint32_t)__bfloat16_as_ushort(a);
}
__device__ __forceinline__ void mma16816(float* c, const uint32_t* a, uint32_t b0, uint32_t b1) {
    asm volatile(
        "mma.sync.aligned.m16n8k16.row.col.f32.bf16.bf16.f32 "
        "{%0,%1,%2,%3}, {%4,%5,%6,%7}, {%8,%9}, {%0,%1,%2,%3};"
        : "+f"(c[0]), "+f"(c[1]), "+f"(c[2]), "+f"(c[3])
        : "r"(a[0]), "r"(a[1]), "r"(a[2]), "r"(a[3]), "r"(b0), "r"(b1));
}

// ---------------- preprocessing ----------------
__global__ void k_zero_detect(const unsigned int* __restrict__ ei) {
    int i = blockIdx.x * blockDim.x + threadIdx.x;
    for (int j = i; j < NN; j += gridDim.x * blockDim.x) g_deg[j] = 0;
    if (blockIdx.x == 0 && threadIdx.x < 32) {
        int lane = threadIdx.x;
        unsigned int nz = 0;
#pragma unroll
        for (int k = 0; k < 4; k++) nz |= ei[2 * (lane * 4 + k) + 1];
        unsigned int any = __ballot_sync(0xffffffffu, nz != 0u);
        if (lane == 0) g_is64 = (any == 0u) ? 1 : 0;
    }
}

__global__ void k_convert(const void* __restrict__ ei) {
    int base = blockIdx.x * 1024 + threadIdx.x;
    int is64 = g_is64;
#pragma unroll
    for (int j = 0; j < 4; j++) {
        int e = base + j * 256;
        int s, d;
        if (is64) {
            const long long* p = (const long long*)ei;
            s = (int)p[e];
            d = (int)p[EE + e];
        } else {
            const int* p = (const int*)ei;
            s = p[e];
            d = p[EE + e];
        }
        g_src[e] = s;
        g_dst[e] = d;
        atomicAdd(&g_deg[d], 1);
    }
}

// coalesced 2-phase scan: A) per-block (1024) exclusive scan + block sums
__global__ void __launch_bounds__(1024) k_scanA() {
    __shared__ int sh[1024];
    int tid = threadIdx.x, bb = blockIdx.x;
    int idx = bb * 1024 + tid;
    int v = g_deg[idx];
    sh[tid] = v;
    __syncthreads();
    for (int off = 1; off < 1024; off <<= 1) {
        int x = (tid >= off) ? sh[tid - off] : 0;
        __syncthreads();
        sh[tid] += x;
        __syncthreads();
    }
    g_excl[idx] = sh[tid] - v;              // exclusive within block
    if (tid == 1023) g_bsum[bb] = sh[1023];
}

// B) add block-prefix, write g_off/g_cur (+ total)
__global__ void __launch_bounds__(1024) k_scanB() {
    __shared__ int base;
    int tid = threadIdx.x, bb = blockIdx.x;
    if (tid < 32) {
        int v = 0;
        // lane l sums g_bsum[2l], g_bsum[2l+1] if below bb
        int i0 = tid * 2, i1 = tid * 2 + 1;
        if (i0 < bb) v += g_bsum[i0];
        if (i1 < bb) v += g_bsum[i1];
#pragma unroll
        for (int off = 16; off > 0; off >>= 1) v += __shfl_xor_sync(0xffffffffu, v, off);
        if (tid == 0) base = v;
    }
    __syncthreads();
    int idx = bb * 1024 + tid;
    int o = base + g_excl[idx];
    g_off[idx] = o;
    g_cur[idx] = o;
    if (bb == 63 && tid == 1023) g_off[NN] = o + g_deg[idx];
}

__global__ void k_csr() {
    int base = blockIdx.x * 1024 + threadIdx.x;
#pragma unroll
    for (int j = 0; j < 4; j++) {
        int e = base + j * 256;
        int pos = atomicAdd(&g_cur[g_dst[e]], 1);
        g_csr[pos] = g_src[e];
    }
}

// ---------------- fused HMMA GEMM + attention dots ----------------
template <int NB, int HEADS_T, int HC>
__global__ void __launch_bounds__(256, 2) k_mma(
    const float* __restrict__ A, const float* __restrict__ Wsrc,
    const float* __restrict__ ats, const float* __restrict__ atd,
    float* __restrict__ Hout, float* __restrict__ as_out, float* __restrict__ ad_out) {
    constexpr int PITCH = 72;
    constexpr int BPW = (NB == 128) ? 136 : 72;
    constexpr int NT = NB / 8;
    extern __shared__ __align__(16) char smem[];
    __nv_bfloat16* Ah = (__nv_bfloat16*)smem;
    __nv_bfloat16* Al = Ah + 128 * PITCH;
    uint32_t* BPh = (uint32_t*)(Al + 128 * PITCH);
    uint32_t* BPl = BPh + 32 * BPW;
    float* s_as = (float*)(BPl + 32 * BPW);
    float* s_ad = s_as + NB;

    int t = threadIdx.x, w = t >> 5, lane = t & 31;
    int gid = lane >> 2, tid4 = lane & 3;
    int row0 = blockIdx.x * 128;
    int wr = w * 16;
    int r1 = wr + gid, r2 = r1 + 8;

    for (int idx = t; idx < NB; idx += 256) {
        s_as[idx] = ats[idx];
        s_ad[idx] = atd[idx];
    }

    float acc[NT][4];
#pragma unroll
    for (int nt = 0; nt < NT; nt++) {
        acc[nt][0] = 0.f; acc[nt][1] = 0.f; acc[nt][2] = 0.f; acc[nt][3] = 0.f;
    }

#pragma unroll
    for (int kc = 0; kc < 2; kc++) {
        if (kc) __syncthreads();
#pragma unroll
        for (int i = 0; i < 8; i++) {
            int idx = i * 256 + t;
            int r = idx >> 4, c4 = idx & 15;
            float4 v = *(const float4*)&A[(size_t)(row0 + r) * 128 + kc * 64 + c4 * 4];
            __nv_bfloat16 hx = __float2bfloat16(v.x), hy = __float2bfloat16(v.y);
            __nv_bfloat16 hz = __float2bfloat16(v.z), hw = __float2bfloat16(v.w);
            __nv_bfloat16 lx = __float2bfloat16(v.x - __bfloat162float(hx));
            __nv_bfloat16 ly = __float2bfloat16(v.y - __bfloat162float(hy));
            __nv_bfloat16 lz = __float2bfloat16(v.z - __bfloat162float(hz));
            __nv_bfloat16 lw = __float2bfloat16(v.w - __bfloat162float(hw));
            int o = r * PITCH + c4 * 4;
            *(uint2*)&Ah[o] = make_uint2(pack_bf2(hx, hy), pack_bf2(hz, hw));
            *(uint2*)&Al[o] = make_uint2(pack_bf2(lx, ly), pack_bf2(lz, lw));
        }
#pragma unroll
        for (int idx = t; idx < 32 * (NB / 4); idx += 256) {
            int k2 = idx / (NB / 4), n4 = idx % (NB / 4);
            const float* wr0 = &Wsrc[(size_t)(kc * 64 + 2 * k2) * NB + n4 * 4];
            float4 w0 = *(const float4*)wr0;
            float4 w1 = *(const float4*)(wr0 + NB);
            float f0[4] = {w0.x, w0.y, w0.z, w0.w};
            float f1[4] = {w1.x, w1.y, w1.z, w1.w};
            uint32_t ph[4], pl[4];
#pragma unroll
            for (int j = 0; j < 4; j++) {
                __nv_bfloat16 h0 = __float2bfloat16(f0[j]);
                __nv_bfloat16 h1 = __float2bfloat16(f1[j]);
                __nv_bfloat16 l0 = __float2bfloat16(f0[j] - __bfloat162float(h0));
                __nv_bfloat16 l1 = __float2bfloat16(f1[j] - __bfloat162float(h1));
                ph[j] = pack_bf2(h0, h1);
                pl[j] = pack_bf2(l0, l1);
            }
            *(uint4*)&BPh[k2 * BPW + n4 * 4] = make_uint4(ph[0], ph[1], ph[2], ph[3]);
            *(uint4*)&BPl[k2 * BPW + n4 * 4] = make_uint4(pl[0], pl[1], pl[2], pl[3]);
        }
        __syncthreads();

#pragma unroll
        for (int kt = 0; kt < 4; kt++) {
            int k0 = kt * 16 + tid4 * 2;
            int p0 = kt * 8 + tid4;
            uint32_t ah[4], al[4];
            ah[0] = *(const uint32_t*)&Ah[r1 * PITCH + k0];
            ah[1] = *(const uint32_t*)&Ah[r2 * PITCH + k0];
            ah[2] = *(const uint32_t*)&Ah[r1 * PITCH + k0 + 8];
            ah[3] = *(const uint32_t*)&Ah[r2 * PITCH + k0 + 8];
            al[0] = *(const uint32_t*)&Al[r1 * PITCH + k0];
            al[1] = *(const uint32_t*)&Al[r2 * PITCH + k0];
            al[2] = *(const uint32_t*)&Al[r1 * PITCH + k0 + 8];
            al[3] = *(const uint32_t*)&Al[r2 * PITCH + k0 + 8];
#pragma unroll
            for (int nt = 0; nt < NT; nt++) {
                int nr = nt * 8 + gid;
                uint32_t bh0 = BPh[p0 * BPW + nr];
                uint32_t bh1 = BPh[(p0 + 4) * BPW + nr];
                uint32_t bl0 = BPl[p0 * BPW + nr];
                uint32_t bl1 = BPl[(p0 + 4) * BPW + nr];
                mma16816(acc[nt], ah, bh0, bh1);
                mma16816(acc[nt], ah, bl0, bl1);
                mma16816(acc[nt], al, bh0, bh1);
            }
        }
    }

    float accs[2][HEADS_T], accd[2][HEADS_T];
#pragma unroll
    for (int i = 0; i < 2; i++)
#pragma unroll
        for (int h = 0; h < HEADS_T; h++) { accs[i][h] = 0.f; accd[i][h] = 0.f; }

    int gr1 = row0 + r1, gr2 = row0 + r2;
#pragma unroll
    for (int nt = 0; nt < NT; nt++) {
        const int hidx = (nt * 8) / HC;
        int c0 = nt * 8 + tid4 * 2;
        float as0 = s_as[c0], as1 = s_as[c0 + 1];
        float ad0 = s_ad[c0], ad1 = s_ad[c0 + 1];
        accs[0][hidx] += acc[nt][0] * as0 + acc[nt][1] * as1;
        accd[0][hidx] += acc[nt][0] * ad0 + acc[nt][1] * ad1;
        accs[1][hidx] += acc[nt][2] * as0 + acc[nt][3] * as1;
        accd[1][hidx] += acc[nt][2] * ad0 + acc[nt][3] * ad1;
        *(float2*)&Hout[(size_t)gr1 * NB + c0] = make_float2(acc[nt][0], acc[nt][1]);
        *(float2*)&Hout[(size_t)gr2 * NB + c0] = make_float2(acc[nt][2], acc[nt][3]);
    }
#pragma unroll
    for (int off = 1; off <= 2; off <<= 1) {
#pragma unroll
        for (int i = 0; i < 2; i++)
#pragma unroll
            for (int h = 0; h < HEADS_T; h++) {
                accs[i][h] += __shfl_xor_sync(0xffffffffu, accs[i][h], off);
                accd[i][h] += __shfl_xor_sync(0xffffffffu, accd[i][h], off);
            }
    }
    if (tid4 == 0) {
#pragma unroll
        for (int h = 0; h < HEADS_T; h++) {
            as_out[(size_t)gr1 * HEADS_T + h] = accs[0][h];
            ad_out[(size_t)gr1 * HEADS_T + h] = accd[0][h];
            as_out[(size_t)gr2 * HEADS_T + h] = accs[1][h];
            ad_out[(size_t)gr2 * HEADS_T + h] = accd[1][h];
        }
    }
}

// ---------------- layer-1 aggregation: lane-owns-float4, 4x unrolled MLP ----------------
__global__ void k_agg1(const float* __restrict__ h, const float* __restrict__ b,
                       float* __restrict__ out) {
    int n = (blockIdx.x * blockDim.x + threadIdx.x) >> 5;
    int lane = threadIdx.x & 31;
    if (n >= NN) return;
    int hsel = lane >> 3;
    int beg = g_off[n], end = g_off[n + 1];
    float4 ad = *(const float4*)&g_ad1[n * 4];

    float4 acc = make_float4(0.f, 0.f, 0.f, 0.f);
    float d0 = 0.f, d1 = 0.f, d2 = 0.f, d3 = 0.f;

    for (int e0 = beg; e0 < end; e0 += 32) {
        int cnt = min(32, end - e0);
        int s = 0;
        float w0 = 0.f, w1 = 0.f, w2 = 0.f, w3 = 0.f;
        if (lane < cnt) {
            s = g_csr[e0 + lane];
            float4 as = *(const float4*)&g_as1[s * 4];
            w0 = __expf(lrelu(as.x + ad.x));
            w1 = __expf(lrelu(as.y + ad.y));
            w2 = __expf(lrelu(as.z + ad.z));
            w3 = __expf(lrelu(as.w + ad.w));
            d0 += w0; d1 += w1; d2 += w2; d3 += w3;
        }
        int j = 0;
        for (; j + 4 <= cnt; j += 4) {
            int sj[4];
            float uq[4];
            float4 v[4];
#pragma unroll
            for (int q = 0; q < 4; q++) {
                int ln = j + q;
                sj[q] = __shfl_sync(0xffffffffu, s, ln);
                float u0 = __shfl_sync(0xffffffffu, w0, ln);
                float u1 = __shfl_sync(0xffffffffu, w1, ln);
                float u2 = __shfl_sync(0xffffffffu, w2, ln);
                float u3 = __shfl_sync(0xffffffffu, w3, ln);
                uq[q] = (hsel < 2) ? (hsel == 0 ? u0 : u1) : (hsel == 2 ? u2 : u3);
            }
#pragma unroll
            for (int q = 0; q < 4; q++)
                v[q] = *(const float4*)&h[(size_t)sj[q] * 128 + lane * 4];
#pragma unroll
            for (int q = 0; q < 4; q++) {
                acc.x += uq[q] * v[q].x;
                acc.y += uq[q] * v[q].y;
                acc.z += uq[q] * v[q].z;
                acc.w += uq[q] * v[q].w;
            }
        }
        for (; j < cnt; j++) {
            int sj = __shfl_sync(0xffffffffu, s, j);
            float u0 = __shfl_sync(0xffffffffu, w0, j);
            float u1 = __shfl_sync(0xffffffffu, w1, j);
            float u2 = __shfl_sync(0xffffffffu, w2, j);
            float u3 = __shfl_sync(0xffffffffu, w3, j);
            float uq = (hsel < 2) ? (hsel == 0 ? u0 : u1) : (hsel == 2 ? u2 : u3);
            float4 v = *(const float4*)&h[(size_t)sj * 128 + lane * 4];
            acc.x += uq * v.x;
            acc.y += uq * v.y;
            acc.z += uq * v.z;
            acc.w += uq * v.w;
        }
    }
#pragma unroll
    for (int off = 16; off > 0; off >>= 1) {
        d0 += __shfl_xor_sync(0xffffffffu, d0, off);
        d1 += __shfl_xor_sync(0xffffffffu, d1, off);
        d2 += __shfl_xor_sync(0xffffffffu, d2, off);
        d3 += __shfl_xor_sync(0xffffffffu, d3, off);
    }
    float dsel = (hsel < 2) ? (hsel == 0 ? d0 : d1) : (hsel == 2 ? d2 : d3);
    float r = 1.f / (dsel + EPSV);
    float4 bv = *(const float4*)&b[lane * 4];
    float4 o;
    o.x = sigm(acc.x * r + bv.x);
    o.y = sigm(acc.y * r + bv.y);
    o.z = sigm(acc.z * r + bv.z);
    o.w = sigm(acc.w * r + bv.w);
    *(float4*)&out[(size_t)n * 128 + lane * 4] = o;
}

// ---------------- layer-2 aggregation: lane-owns-float2, 4x unrolled ----------------
__global__ void k_agg2(const float* __restrict__ h, const float* __restrict__ b,
                       float* __restrict__ out) {
    int n = (blockIdx.x * blockDim.x + threadIdx.x) >> 5;
    int lane = threadIdx.x & 31;
    if (n >= NN) return;
    int beg = g_off[n], end = g_off[n + 1];
    float ad = g_ad2[n];

    float2 acc = make_float2(0.f, 0.f);
    float d = 0.f;
    for (int e0 = beg; e0 < end; e0 += 32) {
        int cnt = min(32, end - e0);
        int s = 0;
        float w = 0.f;
        if (lane < cnt) {
            s = g_csr[e0 + lane];
            w = __expf(lrelu(g_as2[s] + ad));
            d += w;
        }
        int j = 0;
        for (; j + 4 <= cnt; j += 4) {
            int sj[4];
            float u[4];
            float2 v[4];
#pragma unroll
            for (int q = 0; q < 4; q++) {
                sj[q] = __shfl_sync(0xffffffffu, s, j + q);
                u[q] = __shfl_sync(0xffffffffu, w, j + q);
            }
#pragma unroll
            for (int q = 0; q < 4; q++)
                v[q] = *(const float2*)&h[(size_t)sj[q] * 64 + lane * 2];
#pragma unroll
            for (int q = 0; q < 4; q++) {
                acc.x += u[q] * v[q].x;
                acc.y += u[q] * v[q].y;
            }
        }
        for (; j < cnt; j++) {
            int sj = __shfl_sync(0xffffffffu, s, j);
            float u = __shfl_sync(0xffffffffu, w, j);
            float2 v = *(const float2*)&h[(size_t)sj * 64 + lane * 2];
            acc.x += u * v.x;
            acc.y += u * v.y;
        }
    }
#pragma unroll
    for (int off = 16; off > 0; off >>= 1)
        d += __shfl_xor_sync(0xffffffffu, d, off);
    float r = 1.f / (d + EPSV);
    float2 bv = *(const float2*)&b[lane * 2];
    float2 o;
    o.x = sigm(acc.x * r + bv.x);
    o.y = sigm(acc.y * r + bv.y);
    *(float2*)&out[(size_t)n * 64 + lane * 2] = o;
}

// ---------------- launch ----------------
extern "C" void kernel_launch(void* const* d_in, const int* in_sizes, int n_in,
                              void* d_out, int out_size) {
    const float* x     = (const float*)d_in[0];
    const void*  ei    = d_in[1];
    const float* W1    = (const float*)d_in[2];
    const float* at_s1 = (const float*)d_in[3];
    const float* at_d1 = (const float*)d_in[4];
    const float* b1    = (const float*)d_in[5];
    const float* W2    = (const float*)d_in[6];
    const float* at_s2 = (const float*)d_in[7];
    const float* at_d2 = (const float*)d_in[8];
    const float* b2    = (const float*)d_in[9];
    float* out = (float*)d_out;

    float *h1p, *out1p, *h2p, *as1p, *ad1p, *as2p, *ad2p;
    cudaGetSymbolAddress((void**)&h1p, g_h1);
    cudaGetSymbolAddress((void**)&out1p, g_out1);
    cudaGetSymbolAddress((void**)&h2p, g_h2);
    cudaGetSymbolAddress((void**)&as1p, g_as1);
    cudaGetSymbolAddress((void**)&ad1p, g_ad1);
    cudaGetSymbolAddress((void**)&as2p, g_as2);
    cudaGetSymbolAddress((void**)&ad2p, g_ad2);

    const int SM1 = 4 * 128 * 72 * 2 / 2 * 2 + 2 * 32 * 136 * 4 + 2 * 128 * 4;  // 72704
    const int SM2 = 2 * 128 * 72 * 2 + 2 * 32 * 72 * 4 + 2 * 64 * 4;            // 55808
    cudaFuncSetAttribute(k_mma<128, 4, 32>, cudaFuncAttributeMaxDynamicSharedMemorySize, SM1);
    cudaFuncSetAttribute(k_mma<64, 1, 64>, cudaFuncAttributeMaxDynamicSharedMemorySize, SM2);

    // mma1 kept at launch index 3 for the ncu capture window.
    k_zero_detect<<<256, 256>>>((const unsigned int*)ei);               // 0
    k_convert<<<EE / 1024, 256>>>(ei);                                  // 1
    k_scanA<<<64, 1024>>>();                                            // 2
    k_mma<128, 4, 32><<<NN / 128, 256, SM1>>>(x, W1, at_s1, at_d1,      // 3
                                              h1p, as1p, ad1p);
    k_scanB<<<64, 1024>>>();                                            // 4
    k_csr<<<EE / 1024, 256>>>();                                        // 5
    k_agg1<<<NN / 8, 256>>>(h1p, b1, out1p);                            // 6
    k_mma<64, 1, 64><<<NN / 128, 256, SM2>>>(out1p, W2, at_s2, at_d2,   // 7
                                             h2p, as2p, ad2p);
    k_agg2<<<NN / 8, 256>>>(h2p, b2, out);                              // 8
}

// round 14
// speedup vs baseline: 2.6825x; 1.0494x over previous
#include <cuda_runtime.h>
#include <cuda_bf16.h>
#include <stdint.h>
#include <math.h>

#define NN 65536
#define EE 1048576
#define NEG 0.2f
#define EPSV 1e-16f

// ---------------- scratch (device globals: allocation-free) ----------------
__device__ int   g_is64;
__device__ int   g_deg[NN];
__device__ int   g_excl[NN];
__device__ int   g_bsum[64];
__device__ int   g_off[NN + 1];
__device__ int   g_cur[NN];
__device__ int   g_csr[EE];
__device__ float g_h1[NN * 128];
__device__ float g_as1[NN * 4];
__device__ float g_ad1[NN * 4];
__device__ float g_out1[NN * 128];
__device__ float g_h2[NN * 64];
__device__ float g_as2[NN];
__device__ float g_ad2[NN];

__device__ __forceinline__ float lrelu(float a) { return a > 0.f ? a : NEG * a; }
__device__ __forceinline__ float sigm(float x) { return 1.f / (1.f + __expf(-x)); }
__device__ __forceinline__ uint32_t pack_bf2(__nv_bfloat16 a, __nv_bfloat16 b) {
    return ((uint32_t)__bfloat16_as_ushort(b) << 16) | (uint32_t)__bfloat16_as_ushort(a);
}
__device__ __forceinline__ void mma16816(float* c, const uint32_t* a, uint32_t b0, uint32_t b1) {
    asm volatile(
        "mma.sync.aligned.m16n8k16.row.col.f32.bf16.bf16.f32 "
        "{%0,%1,%2,%3}, {%4,%5,%6,%7}, {%8,%9}, {%0,%1,%2,%3};"
        : "+f"(c[0]), "+f"(c[1]), "+f"(c[2]), "+f"(c[3])
        : "r"(a[0]), "r"(a[1]), "r"(a[2]), "r"(a[3]), "r"(b0), "r"(b1));
}

// ---------------- preprocessing ----------------
__global__ void k_zero_detect(const unsigned int* __restrict__ ei) {
    int i = blockIdx.x * blockDim.x + threadIdx.x;
    for (int j = i; j < NN; j += gridDim.x * blockDim.x) g_deg[j] = 0;
    if (blockIdx.x == 0 && threadIdx.x < 32) {
        int lane = threadIdx.x;
        unsigned int nz = 0;
#pragma unroll
        for (int k = 0; k < 4; k++) nz |= ei[2 * (lane * 4 + k) + 1];
        unsigned int any = __ballot_sync(0xffffffffu, nz != 0u);
        if (lane == 0) g_is64 = (any == 0u) ? 1 : 0;
    }
}

// degree histogram only (dst half of edge list)
__global__ void k_degree(const void* __restrict__ ei) {
    int base = blockIdx.x * 1024 + threadIdx.x;
    int is64 = g_is64;
#pragma unroll
    for (int j = 0; j < 4; j++) {
        int e = base + j * 256;
        int d = is64 ? (int)((const long long*)ei)[EE + e] : ((const int*)ei)[EE + e];
        atomicAdd(&g_deg[d], 1);
    }
}

// coalesced 2-phase scan
__global__ void __launch_bounds__(1024) k_scanA() {
    __shared__ int sh[1024];
    int tid = threadIdx.x, bb = blockIdx.x;
    int idx = bb * 1024 + tid;
    int v = g_deg[idx];
    sh[tid] = v;
    __syncthreads();
    for (int off = 1; off < 1024; off <<= 1) {
        int x = (tid >= off) ? sh[tid - off] : 0;
        __syncthreads();
        sh[tid] += x;
        __syncthreads();
    }
    g_excl[idx] = sh[tid] - v;
    if (tid == 1023) g_bsum[bb] = sh[1023];
}

__global__ void __launch_bounds__(1024) k_scanB() {
    __shared__ int base;
    int tid = threadIdx.x, bb = blockIdx.x;
    if (tid < 32) {
        int v = 0;
        int i0 = tid * 2, i1 = tid * 2 + 1;
        if (i0 < bb) v += g_bsum[i0];
        if (i1 < bb) v += g_bsum[i1];
#pragma unroll
        for (int off = 16; off > 0; off >>= 1) v += __shfl_xor_sync(0xffffffffu, v, off);
        if (tid == 0) base = v;
    }
    __syncthreads();
    int idx = bb * 1024 + tid;
    int o = base + g_excl[idx];
    g_off[idx] = o;
    g_cur[idx] = o;
    if (bb == 63 && tid == 1023) g_off[NN] = o + g_deg[idx];
}

// CSR fill straight from the edge list (no src/dst staging)
__global__ void k_csr(const void* __restrict__ ei) {
    int base = blockIdx.x * 1024 + threadIdx.x;
    int is64 = g_is64;
#pragma unroll
    for (int j = 0; j < 4; j++) {
        int e = base + j * 256;
        int s, d;
        if (is64) {
            const long long* p = (const long long*)ei;
            s = (int)p[e];
            d = (int)p[EE + e];
        } else {
            const int* p = (const int*)ei;
            s = p[e];
            d = p[EE + e];
        }
        int pos = atomicAdd(&g_cur[d], 1);
        g_csr[pos] = s;
    }
}

// ---------------- fused HMMA GEMM + attention dots ----------------
template <int NB, int HEADS_T, int HC>
__global__ void __launch_bounds__(256, 2) k_mma(
    const float* __restrict__ A, const float* __restrict__ Wsrc,
    const float* __restrict__ ats, const float* __restrict__ atd,
    float* __restrict__ Hout, float* __restrict__ as_out, float* __restrict__ ad_out) {
    constexpr int PITCH = 72;
    constexpr int BPW = (NB == 128) ? 136 : 72;
    constexpr int NT = NB / 8;
    extern __shared__ __align__(16) char smem[];
    __nv_bfloat16* Ah = (__nv_bfloat16*)smem;
    __nv_bfloat16* Al = Ah + 128 * PITCH;
    uint32_t* BPh = (uint32_t*)(Al + 128 * PITCH);
    uint32_t* BPl = BPh + 32 * BPW;
    float* s_as = (float*)(BPl + 32 * BPW);
    float* s_ad = s_as + NB;

    int t = threadIdx.x, w = t >> 5, lane = t & 31;
    int gid = lane >> 2, tid4 = lane & 3;
    int row0 = blockIdx.x * 128;
    int wr = w * 16;
    int r1 = wr + gid, r2 = r1 + 8;

    for (int idx = t; idx < NB; idx += 256) {
        s_as[idx] = ats[idx];
        s_ad[idx] = atd[idx];
    }

    float acc[NT][4];
#pragma unroll
    for (int nt = 0; nt < NT; nt++) {
        acc[nt][0] = 0.f; acc[nt][1] = 0.f; acc[nt][2] = 0.f; acc[nt][3] = 0.f;
    }

#pragma unroll
    for (int kc = 0; kc < 2; kc++) {
        if (kc) __syncthreads();
#pragma unroll
        for (int i = 0; i < 8; i++) {
            int idx = i * 256 + t;
            int r = idx >> 4, c4 = idx & 15;
            float4 v = *(const float4*)&A[(size_t)(row0 + r) * 128 + kc * 64 + c4 * 4];
            __nv_bfloat16 hx = __float2bfloat16(v.x), hy = __float2bfloat16(v.y);
            __nv_bfloat16 hz = __float2bfloat16(v.z), hw = __float2bfloat16(v.w);
            __nv_bfloat16 lx = __float2bfloat16(v.x - __bfloat162float(hx));
            __nv_bfloat16 ly = __float2bfloat16(v.y - __bfloat162float(hy));
            __nv_bfloat16 lz = __float2bfloat16(v.z - __bfloat162float(hz));
            __nv_bfloat16 lw = __float2bfloat16(v.w - __bfloat162float(hw));
            int o = r * PITCH + c4 * 4;
            *(uint2*)&Ah[o] = make_uint2(pack_bf2(hx, hy), pack_bf2(hz, hw));
            *(uint2*)&Al[o] = make_uint2(pack_bf2(lx, ly), pack_bf2(lz, lw));
        }
#pragma unroll
        for (int idx = t; idx < 32 * (NB / 4); idx += 256) {
            int k2 = idx / (NB / 4), n4 = idx % (NB / 4);
            const float* wr0 = &Wsrc[(size_t)(kc * 64 + 2 * k2) * NB + n4 * 4];
            float4 w0 = *(const float4*)wr0;
            float4 w1 = *(const float4*)(wr0 + NB);
            float f0[4] = {w0.x, w0.y, w0.z, w0.w};
            float f1[4] = {w1.x, w1.y, w1.z, w1.w};
            uint32_t ph[4], pl[4];
#pragma unroll
            for (int j = 0; j < 4; j++) {
                __nv_bfloat16 h0 = __float2bfloat16(f0[j]);
                __nv_bfloat16 h1 = __float2bfloat16(f1[j]);
                __nv_bfloat16 l0 = __float2bfloat16(f0[j] - __bfloat162float(h0));
                __nv_bfloat16 l1 = __float2bfloat16(f1[j] - __bfloat162float(h1));
                ph[j] = pack_bf2(h0, h1);
                pl[j] = pack_bf2(l0, l1);
            }
            *(uint4*)&BPh[k2 * BPW + n4 * 4] = make_uint4(ph[0], ph[1], ph[2], ph[3]);
            *(uint4*)&BPl[k2 * BPW + n4 * 4] = make_uint4(pl[0], pl[1], pl[2], pl[3]);
        }
        __syncthreads();

#pragma unroll
        for (int kt = 0; kt < 4; kt++) {
            int k0 = kt * 16 + tid4 * 2;
            int p0 = kt * 8 + tid4;
            uint32_t ah[4], al[4];
            ah[0] = *(const uint32_t*)&Ah[r1 * PITCH + k0];
            ah[1] = *(const uint32_t*)&Ah[r2 * PITCH + k0];
            ah[2] = *(const uint32_t*)&Ah[r1 * PITCH + k0 + 8];
            ah[3] = *(const uint32_t*)&Ah[r2 * PITCH + k0 + 8];
            al[0] = *(const uint32_t*)&Al[r1 * PITCH + k0];
            al[1] = *(const uint32_t*)&Al[r2 * PITCH + k0];
            al[2] = *(const uint32_t*)&Al[r1 * PITCH + k0 + 8];
            al[3] = *(const uint32_t*)&Al[r2 * PITCH + k0 + 8];
#pragma unroll
            for (int nt = 0; nt < NT; nt++) {
                int nr = nt * 8 + gid;
                uint32_t bh0 = BPh[p0 * BPW + nr];
                uint32_t bh1 = BPh[(p0 + 4) * BPW + nr];
                uint32_t bl0 = BPl[p0 * BPW + nr];
                uint32_t bl1 = BPl[(p0 + 4) * BPW + nr];
                mma16816(acc[nt], ah, bh0, bh1);
                mma16816(acc[nt], ah, bl0, bl1);
                mma16816(acc[nt], al, bh0, bh1);
            }
        }
    }

    float accs[2][HEADS_T], accd[2][HEADS_T];
#pragma unroll
    for (int i = 0; i < 2; i++)
#pragma unroll
        for (int h = 0; h < HEADS_T; h++) { accs[i][h] = 0.f; accd[i][h] = 0.f; }

    int gr1 = row0 + r1, gr2 = row0 + r2;
#pragma unroll
    for (int nt = 0; nt < NT; nt++) {
        const int hidx = (nt * 8) / HC;
        int c0 = nt * 8 + tid4 * 2;
        float as0 = s_as[c0], as1 = s_as[c0 + 1];
        float ad0 = s_ad[c0], ad1 = s_ad[c0 + 1];
        accs[0][hidx] += acc[nt][0] * as0 + acc[nt][1] * as1;
        accd[0][hidx] += acc[nt][0] * ad0 + acc[nt][1] * ad1;
        accs[1][hidx] += acc[nt][2] * as0 + acc[nt][3] * as1;
        accd[1][hidx] += acc[nt][2] * ad0 + acc[nt][3] * ad1;
        *(float2*)&Hout[(size_t)gr1 * NB + c0] = make_float2(acc[nt][0], acc[nt][1]);
        *(float2*)&Hout[(size_t)gr2 * NB + c0] = make_float2(acc[nt][2], acc[nt][3]);
    }
#pragma unroll
    for (int off = 1; off <= 2; off <<= 1) {
#pragma unroll
        for (int i = 0; i < 2; i++)
#pragma unroll
            for (int h = 0; h < HEADS_T; h++) {
                accs[i][h] += __shfl_xor_sync(0xffffffffu, accs[i][h], off);
                accd[i][h] += __shfl_xor_sync(0xffffffffu, accd[i][h], off);
            }
    }
    if (tid4 == 0) {
#pragma unroll
        for (int h = 0; h < HEADS_T; h++) {
            as_out[(size_t)gr1 * HEADS_T + h] = accs[0][h];
            ad_out[(size_t)gr1 * HEADS_T + h] = accd[0][h];
            as_out[(size_t)gr2 * HEADS_T + h] = accs[1][h];
            ad_out[(size_t)gr2 * HEADS_T + h] = accd[1][h];
        }
    }
}

// ---------------- layer-1 aggregation ----------------
__global__ void k_agg1(const float* __restrict__ h, const float* __restrict__ b,
                       float* __restrict__ out) {
    int n = (blockIdx.x * blockDim.x + threadIdx.x) >> 5;
    int lane = threadIdx.x & 31;
    if (n >= NN) return;
    int hsel = lane >> 3;
    int beg = g_off[n], end = g_off[n + 1];
    float4 ad = *(const float4*)&g_ad1[n * 4];

    float4 acc = make_float4(0.f, 0.f, 0.f, 0.f);
    float d0 = 0.f, d1 = 0.f, d2 = 0.f, d3 = 0.f;

    for (int e0 = beg; e0 < end; e0 += 32) {
        int cnt = min(32, end - e0);
        int s = 0;
        float w0 = 0.f, w1 = 0.f, w2 = 0.f, w3 = 0.f;
        if (lane < cnt) {
            s = g_csr[e0 + lane];
            float4 as = *(const float4*)&g_as1[s * 4];
            w0 = __expf(lrelu(as.x + ad.x));
            w1 = __expf(lrelu(as.y + ad.y));
            w2 = __expf(lrelu(as.z + ad.z));
            w3 = __expf(lrelu(as.w + ad.w));
            d0 += w0; d1 += w1; d2 += w2; d3 += w3;
        }
        int j = 0;
        for (; j + 4 <= cnt; j += 4) {
            int sj[4];
            float uq[4];
            float4 v[4];
#pragma unroll
            for (int q = 0; q < 4; q++) {
                int ln = j + q;
                sj[q] = __shfl_sync(0xffffffffu, s, ln);
                float u0 = __shfl_sync(0xffffffffu, w0, ln);
                float u1 = __shfl_sync(0xffffffffu, w1, ln);
                float u2 = __shfl_sync(0xffffffffu, w2, ln);
                float u3 = __shfl_sync(0xffffffffu, w3, ln);
                uq[q] = (hsel < 2) ? (hsel == 0 ? u0 : u1) : (hsel == 2 ? u2 : u3);
            }
#pragma unroll
            for (int q = 0; q < 4; q++)
                v[q] = *(const float4*)&h[(size_t)sj[q] * 128 + lane * 4];
#pragma unroll
            for (int q = 0; q < 4; q++) {
                acc.x += uq[q] * v[q].x;
                acc.y += uq[q] * v[q].y;
                acc.z += uq[q] * v[q].z;
                acc.w += uq[q] * v[q].w;
            }
        }
        for (; j < cnt; j++) {
            int sj = __shfl_sync(0xffffffffu, s, j);
            float u0 = __shfl_sync(0xffffffffu, w0, j);
            float u1 = __shfl_sync(0xffffffffu, w1, j);
            float u2 = __shfl_sync(0xffffffffu, w2, j);
            float u3 = __shfl_sync(0xffffffffu, w3, j);
            float uq = (hsel < 2) ? (hsel == 0 ? u0 : u1) : (hsel == 2 ? u2 : u3);
            float4 v = *(const float4*)&h[(size_t)sj * 128 + lane * 4];
            acc.x += uq * v.x;
            acc.y += uq * v.y;
            acc.z += uq * v.z;
            acc.w += uq * v.w;
        }
    }
#pragma unroll
    for (int off = 16; off > 0; off >>= 1) {
        d0 += __shfl_xor_sync(0xffffffffu, d0, off);
        d1 += __shfl_xor_sync(0xffffffffu, d1, off);
        d2 += __shfl_xor_sync(0xffffffffu, d2, off);
        d3 += __shfl_xor_sync(0xffffffffu, d3, off);
    }
    float dsel = (hsel < 2) ? (hsel == 0 ? d0 : d1) : (hsel == 2 ? d2 : d3);
    float r = 1.f / (dsel + EPSV);
    float4 bv = *(const float4*)&b[lane * 4];
    float4 o;
    o.x = sigm(acc.x * r + bv.x);
    o.y = sigm(acc.y * r + bv.y);
    o.z = sigm(acc.z * r + bv.z);
    o.w = sigm(acc.w * r + bv.w);
    *(float4*)&out[(size_t)n * 128 + lane * 4] = o;
}

// ---------------- layer-2 aggregation ----------------
__global__ void k_agg2(const float* __restrict__ h, const float* __restrict__ b,
                       float* __restrict__ out) {
    int n = (blockIdx.x * blockDim.x + threadIdx.x) >> 5;
    int lane = threadIdx.x & 31;
    if (n >= NN) return;
    int beg = g_off[n], end = g_off[n + 1];
    float ad = g_ad2[n];

    float2 acc = make_float2(0.f, 0.f);
    float d = 0.f;
    for (int e0 = beg; e0 < end; e0 += 32) {
        int cnt = min(32, end - e0);
        int s = 0;
        float w = 0.f;
        if (lane < cnt) {
            s = g_csr[e0 + lane];
            w = __expf(lrelu(g_as2[s] + ad));
            d += w;
        }
        int j = 0;
        for (; j + 4 <= cnt; j += 4) {
            int sj[4];
            float u[4];
            float2 v[4];
#pragma unroll
            for (int q = 0; q < 4; q++) {
                sj[q] = __shfl_sync(0xffffffffu, s, j + q);
                u[q] = __shfl_sync(0xffffffffu, w, j + q);
            }
#pragma unroll
            for (int q = 0; q < 4; q++)
                v[q] = *(const float2*)&h[(size_t)sj[q] * 64 + lane * 2];
#pragma unroll
            for (int q = 0; q < 4; q++) {
                acc.x += u[q] * v[q].x;
                acc.y += u[q] * v[q].y;
            }
        }
        for (; j < cnt; j++) {
            int sj = __shfl_sync(0xffffffffu, s, j);
            float u = __shfl_sync(0xffffffffu, w, j);
            float2 v = *(const float2*)&h[(size_t)sj * 64 + lane * 2];
            acc.x += u * v.x;
            acc.y += u * v.y;
        }
    }
#pragma unroll
    for (int off = 16; off > 0; off >>= 1)
        d += __shfl_xor_sync(0xffffffffu, d, off);
    float r = 1.f / (d + EPSV);
    float2 bv = *(const float2*)&b[lane * 2];
    float2 o;
    o.x = sigm(acc.x * r + bv.x);
    o.y = sigm(acc.y * r + bv.y);
    *(float2*)&out[(size_t)n * 64 + lane * 2] = o;
}

// ---------------- launch: fork preprocessing onto a side stream ----------------
extern "C" void kernel_launch(void* const* d_in, const int* in_sizes, int n_in,
                              void* d_out, int out_size) {
    const float* x     = (const float*)d_in[0];
    const void*  ei    = d_in[1];
    const float* W1    = (const float*)d_in[2];
    const float* at_s1 = (const float*)d_in[3];
    const float* at_d1 = (const float*)d_in[4];
    const float* b1    = (const float*)d_in[5];
    const float* W2    = (const float*)d_in[6];
    const float* at_s2 = (const float*)d_in[7];
    const float* at_d2 = (const float*)d_in[8];
    const float* b2    = (const float*)d_in[9];
    float* out = (float*)d_out;

    float *h1p, *out1p, *h2p, *as1p, *ad1p, *as2p, *ad2p;
    cudaGetSymbolAddress((void**)&h1p, g_h1);
    cudaGetSymbolAddress((void**)&out1p, g_out1);
    cudaGetSymbolAddress((void**)&h2p, g_h2);
    cudaGetSymbolAddress((void**)&as1p, g_as1);
    cudaGetSymbolAddress((void**)&ad1p, g_ad1);
    cudaGetSymbolAddress((void**)&as2p, g_as2);
    cudaGetSymbolAddress((void**)&ad2p, g_ad2);

    const int SM1 = 4 * 128 * 72 * 2 / 2 * 2 + 2 * 32 * 136 * 4 + 2 * 128 * 4;  // 72704
    const int SM2 = 2 * 128 * 72 * 2 + 2 * 32 * 72 * 4 + 2 * 64 * 4;            // 55808
    cudaFuncSetAttribute(k_mma<128, 4, 32>, cudaFuncAttributeMaxDynamicSharedMemorySize, SM1);
    cudaFuncSetAttribute(k_mma<64, 1, 64>, cudaFuncAttributeMaxDynamicSharedMemorySize, SM2);

    // init-once side stream + events (host-side only; no device allocation)
    static cudaStream_t s2 = nullptr;
    static cudaEvent_t evF = nullptr, evJ = nullptr;
    if (!s2) {
        cudaStreamCreateWithFlags(&s2, cudaStreamNonBlocking);
        cudaEventCreateWithFlags(&evF, cudaEventDisableTiming);
        cudaEventCreateWithFlags(&evJ, cudaEventDisableTiming);
    }

    // fork: preprocessing chain on s2, concurrent with mma1 on the main stream
    cudaEventRecord(evF, 0);
    cudaStreamWaitEvent(s2, evF, 0);

    k_zero_detect<<<256, 256, 0, s2>>>((const unsigned int*)ei);
    k_degree<<<EE / 1024, 256, 0, s2>>>(ei);
    k_scanA<<<64, 1024, 0, s2>>>();
    k_scanB<<<64, 1024, 0, s2>>>();
    k_csr<<<EE / 1024, 256, 0, s2>>>(ei);
    cudaEventRecord(evJ, s2);

    k_mma<128, 4, 32><<<NN / 128, 256, SM1>>>(x, W1, at_s1, at_d1, h1p, as1p, ad1p);

    // join: agg1 needs both CSR (s2) and mma1 (main)
    cudaStreamWaitEvent(0, evJ, 0);
    k_agg1<<<NN / 8, 256>>>(h1p, b1, out1p);
    k_mma<64, 1, 64><<<NN / 128, 256, SM2>>>(out1p, W2, at_s2, at_d2, h2p, as2p, ad2p);
    k_agg2<<<NN / 8, 256>>>(h2p, b2, out);
}

// round 15
// speedup vs baseline: 2.9168x; 1.0873x over previous
#include <cuda_runtime.h>
#include <cuda_bf16.h>
#include <stdint.h>
#include <math.h>

#define NN 65536
#define EE 1048576
#define NEG 0.2f
#define EPSV 1e-16f

// ---------------- scratch (device globals: allocation-free) ----------------
__device__ int      g_is64;
__device__ int      g_deg[NN];
__device__ int      g_excl[NN];
__device__ int      g_bsum[64];
__device__ int      g_off[NN + 1];
__device__ int      g_cur[NN];
__device__ int      g_csr[EE];
__device__ uint16_t g_h1[NN * 128];   // bf16
__device__ float    g_as1[NN * 4];
__device__ float    g_ad1[NN * 4];
__device__ float    g_out1[NN * 128];
__device__ uint16_t g_h2[NN * 64];    // bf16
__device__ float    g_as2[NN];
__device__ float    g_ad2[NN];

__device__ __forceinline__ float lrelu(float a) { return a > 0.f ? a : NEG * a; }
__device__ __forceinline__ float sigm(float x) { return 1.f / (1.f + __expf(-x)); }
__device__ __forceinline__ uint32_t pack_bf2(__nv_bfloat16 a, __nv_bfloat16 b) {
    return ((uint32_t)__bfloat16_as_ushort(b) << 16) | (uint32_t)__bfloat16_as_ushort(a);
}
__device__ __forceinline__ float2 unpack_bf2(uint32_t v) {
    __nv_bfloat162 b = *reinterpret_cast<__nv_bfloat162*>(&v);
    return __bfloat1622float2(b);
}
__device__ __forceinline__ void mma16816(float* c, const uint32_t* a, uint32_t b0, uint32_t b1) {
    asm volatile(
        "mma.sync.aligned.m16n8k16.row.col.f32.bf16.bf16.f32 "
        "{%0,%1,%2,%3}, {%4,%5,%6,%7}, {%8,%9}, {%0,%1,%2,%3};"
        : "+f"(c[0]), "+f"(c[1]), "+f"(c[2]), "+f"(c[3])
        : "r"(a[0]), "r"(a[1]), "r"(a[2]), "r"(a[3]), "r"(b0), "r"(b1));
}

// ---------------- preprocessing ----------------
// 1-warp dtype probe (g_deg zeroing now folded into k_scanB of the previous replay)
__global__ void k_detect(const unsigned int* __restrict__ ei) {
    int lane = threadIdx.x;
    unsigned int nz = 0;
#pragma unroll
    for (int k = 0; k < 4; k++) nz |= ei[2 * (lane * 4 + k) + 1];
    unsigned int any = __ballot_sync(0xffffffffu, nz != 0u);
    if (lane == 0) g_is64 = (any == 0u) ? 1 : 0;
}

__global__ void k_degree(const void* __restrict__ ei) {
    int base = blockIdx.x * 1024 + threadIdx.x;
    int is64 = g_is64;
#pragma unroll
    for (int j = 0; j < 4; j++) {
        int e = base + j * 256;
        int d = is64 ? (int)((const long long*)ei)[EE + e] : ((const int*)ei)[EE + e];
        atomicAdd(&g_deg[d], 1);
    }
}

__global__ void __launch_bounds__(1024) k_scanA() {
    __shared__ int sh[1024];
    int tid = threadIdx.x, bb = blockIdx.x;
    int idx = bb * 1024 + tid;
    int v = g_deg[idx];
    sh[tid] = v;
    __syncthreads();
    for (int off = 1; off < 1024; off <<= 1) {
        int x = (tid >= off) ? sh[tid - off] : 0;
        __syncthreads();
        sh[tid] += x;
        __syncthreads();
    }
    g_excl[idx] = sh[tid] - v;
    if (tid == 1023) g_bsum[bb] = sh[1023];
}

__global__ void __launch_bounds__(1024) k_scanB() {
    __shared__ int base;
    int tid = threadIdx.x, bb = blockIdx.x;
    if (tid < 32) {
        int v = 0;
        int i0 = tid * 2, i1 = tid * 2 + 1;
        if (i0 < bb) v += g_bsum[i0];
        if (i1 < bb) v += g_bsum[i1];
#pragma unroll
        for (int off = 16; off > 0; off >>= 1) v += __shfl_xor_sync(0xffffffffu, v, off);
        if (tid == 0) base = v;
    }
    __syncthreads();
    int idx = bb * 1024 + tid;
    int o = base + g_excl[idx];
    g_off[idx] = o;
    g_cur[idx] = o;
    if (bb == 63 && tid == 1023) g_off[NN] = o + g_deg[idx];
    g_deg[idx] = 0;  // pre-zero for the next replay (deterministic)
}

__global__ void k_csr(const void* __restrict__ ei) {
    int base = blockIdx.x * 1024 + threadIdx.x;
    int is64 = g_is64;
#pragma unroll
    for (int j = 0; j < 4; j++) {
        int e = base + j * 256;
        int s, d;
        if (is64) {
            const long long* p = (const long long*)ei;
            s = (int)p[e];
            d = (int)p[EE + e];
        } else {
            const int* p = (const int*)ei;
            s = p[e];
            d = p[EE + e];
        }
        int pos = atomicAdd(&g_cur[d], 1);
        g_csr[pos] = s;
    }
}

// ---------------- fused HMMA GEMM + attention dots (bf16 H output) ----------------
template <int NB, int HEADS_T, int HC>
__global__ void __launch_bounds__(256, 2) k_mma(
    const float* __restrict__ A, const float* __restrict__ Wsrc,
    const float* __restrict__ ats, const float* __restrict__ atd,
    uint16_t* __restrict__ Hout, float* __restrict__ as_out, float* __restrict__ ad_out) {
    constexpr int PITCH = 72;
    constexpr int BPW = (NB == 128) ? 136 : 72;
    constexpr int NT = NB / 8;
    extern __shared__ __align__(16) char smem[];
    __nv_bfloat16* Ah = (__nv_bfloat16*)smem;
    __nv_bfloat16* Al = Ah + 128 * PITCH;
    uint32_t* BPh = (uint32_t*)(Al + 128 * PITCH);
    uint32_t* BPl = BPh + 32 * BPW;
    float* s_as = (float*)(BPl + 32 * BPW);
    float* s_ad = s_as + NB;

    int t = threadIdx.x, w = t >> 5, lane = t & 31;
    int gid = lane >> 2, tid4 = lane & 3;
    int row0 = blockIdx.x * 128;
    int wr = w * 16;
    int r1 = wr + gid, r2 = r1 + 8;

    for (int idx = t; idx < NB; idx += 256) {
        s_as[idx] = ats[idx];
        s_ad[idx] = atd[idx];
    }

    float acc[NT][4];
#pragma unroll
    for (int nt = 0; nt < NT; nt++) {
        acc[nt][0] = 0.f; acc[nt][1] = 0.f; acc[nt][2] = 0.f; acc[nt][3] = 0.f;
    }

#pragma unroll
    for (int kc = 0; kc < 2; kc++) {
        if (kc) __syncthreads();
#pragma unroll
        for (int i = 0; i < 8; i++) {
            int idx = i * 256 + t;
            int r = idx >> 4, c4 = idx & 15;
            float4 v = *(const float4*)&A[(size_t)(row0 + r) * 128 + kc * 64 + c4 * 4];
            __nv_bfloat16 hx = __float2bfloat16(v.x), hy = __float2bfloat16(v.y);
            __nv_bfloat16 hz = __float2bfloat16(v.z), hw = __float2bfloat16(v.w);
            __nv_bfloat16 lx = __float2bfloat16(v.x - __bfloat162float(hx));
            __nv_bfloat16 ly = __float2bfloat16(v.y - __bfloat162float(hy));
            __nv_bfloat16 lz = __float2bfloat16(v.z - __bfloat162float(hz));
            __nv_bfloat16 lw = __float2bfloat16(v.w - __bfloat162float(hw));
            int o = r * PITCH + c4 * 4;
            *(uint2*)&Ah[o] = make_uint2(pack_bf2(hx, hy), pack_bf2(hz, hw));
            *(uint2*)&Al[o] = make_uint2(pack_bf2(lx, ly), pack_bf2(lz, lw));
        }
#pragma unroll
        for (int idx = t; idx < 32 * (NB / 4); idx += 256) {
            int k2 = idx / (NB / 4), n4 = idx % (NB / 4);
            const float* wr0 = &Wsrc[(size_t)(kc * 64 + 2 * k2) * NB + n4 * 4];
            float4 w0 = *(const float4*)wr0;
            float4 w1 = *(const float4*)(wr0 + NB);
            float f0[4] = {w0.x, w0.y, w0.z, w0.w};
            float f1[4] = {w1.x, w1.y, w1.z, w1.w};
            uint32_t ph[4], pl[4];
#pragma unroll
            for (int j = 0; j < 4; j++) {
                __nv_bfloat16 h0 = __float2bfloat16(f0[j]);
                __nv_bfloat16 h1 = __float2bfloat16(f1[j]);
                __nv_bfloat16 l0 = __float2bfloat16(f0[j] - __bfloat162float(h0));
                __nv_bfloat16 l1 = __float2bfloat16(f1[j] - __bfloat162float(h1));
                ph[j] = pack_bf2(h0, h1);
                pl[j] = pack_bf2(l0, l1);
            }
            *(uint4*)&BPh[k2 * BPW + n4 * 4] = make_uint4(ph[0], ph[1], ph[2], ph[3]);
            *(uint4*)&BPl[k2 * BPW + n4 * 4] = make_uint4(pl[0], pl[1], pl[2], pl[3]);
        }
        __syncthreads();

#pragma unroll
        for (int kt = 0; kt < 4; kt++) {
            int k0 = kt * 16 + tid4 * 2;
            int p0 = kt * 8 + tid4;
            uint32_t ah[4], al[4];
            ah[0] = *(const uint32_t*)&Ah[r1 * PITCH + k0];
            ah[1] = *(const uint32_t*)&Ah[r2 * PITCH + k0];
            ah[2] = *(const uint32_t*)&Ah[r1 * PITCH + k0 + 8];
            ah[3] = *(const uint32_t*)&Ah[r2 * PITCH + k0 + 8];
            al[0] = *(const uint32_t*)&Al[r1 * PITCH + k0];
            al[1] = *(const uint32_t*)&Al[r2 * PITCH + k0];
            al[2] = *(const uint32_t*)&Al[r1 * PITCH + k0 + 8];
            al[3] = *(const uint32_t*)&Al[r2 * PITCH + k0 + 8];
#pragma unroll
            for (int nt = 0; nt < NT; nt++) {
                int nr = nt * 8 + gid;
                uint32_t bh0 = BPh[p0 * BPW + nr];
                uint32_t bh1 = BPh[(p0 + 4) * BPW + nr];
                uint32_t bl0 = BPl[p0 * BPW + nr];
                uint32_t bl1 = BPl[(p0 + 4) * BPW + nr];
                mma16816(acc[nt], ah, bh0, bh1);
                mma16816(acc[nt], ah, bl0, bl1);
                mma16816(acc[nt], al, bh0, bh1);
            }
        }
    }

    float accs[2][HEADS_T], accd[2][HEADS_T];
#pragma unroll
    for (int i = 0; i < 2; i++)
#pragma unroll
        for (int h = 0; h < HEADS_T; h++) { accs[i][h] = 0.f; accd[i][h] = 0.f; }

    int gr1 = row0 + r1, gr2 = row0 + r2;
#pragma unroll
    for (int nt = 0; nt < NT; nt++) {
        const int hidx = (nt * 8) / HC;
        int c0 = nt * 8 + tid4 * 2;
        float as0 = s_as[c0], as1 = s_as[c0 + 1];
        float ad0 = s_ad[c0], ad1 = s_ad[c0 + 1];
        accs[0][hidx] += acc[nt][0] * as0 + acc[nt][1] * as1;
        accd[0][hidx] += acc[nt][0] * ad0 + acc[nt][1] * ad1;
        accs[1][hidx] += acc[nt][2] * as0 + acc[nt][3] * as1;
        accd[1][hidx] += acc[nt][2] * ad0 + acc[nt][3] * ad1;
        // bf16 H rows (dots above already taken from fp32 accumulators)
        *(uint32_t*)&Hout[(size_t)gr1 * NB + c0] =
            pack_bf2(__float2bfloat16(acc[nt][0]), __float2bfloat16(acc[nt][1]));
        *(uint32_t*)&Hout[(size_t)gr2 * NB + c0] =
            pack_bf2(__float2bfloat16(acc[nt][2]), __float2bfloat16(acc[nt][3]));
    }
#pragma unroll
    for (int off = 1; off <= 2; off <<= 1) {
#pragma unroll
        for (int i = 0; i < 2; i++)
#pragma unroll
            for (int h = 0; h < HEADS_T; h++) {
                accs[i][h] += __shfl_xor_sync(0xffffffffu, accs[i][h], off);
                accd[i][h] += __shfl_xor_sync(0xffffffffu, accd[i][h], off);
            }
    }
    if (tid4 == 0) {
#pragma unroll
        for (int h = 0; h < HEADS_T; h++) {
            as_out[(size_t)gr1 * HEADS_T + h] = accs[0][h];
            ad_out[(size_t)gr1 * HEADS_T + h] = accd[0][h];
            as_out[(size_t)gr2 * HEADS_T + h] = accs[1][h];
            ad_out[(size_t)gr2 * HEADS_T + h] = accd[1][h];
        }
    }
}

// ---------------- layer-1 aggregation: bf16 gather (uint2 per edge per lane) ----------------
__global__ void k_agg1(const uint16_t* __restrict__ h, const float* __restrict__ b,
                       float* __restrict__ out) {
    int n = (blockIdx.x * blockDim.x + threadIdx.x) >> 5;
    int lane = threadIdx.x & 31;
    if (n >= NN) return;
    int hsel = lane >> 3;
    int beg = g_off[n], end = g_off[n + 1];
    float4 ad = *(const float4*)&g_ad1[n * 4];

    float4 acc = make_float4(0.f, 0.f, 0.f, 0.f);
    float d0 = 0.f, d1 = 0.f, d2 = 0.f, d3 = 0.f;

    for (int e0 = beg; e0 < end; e0 += 32) {
        int cnt = min(32, end - e0);
        int s = 0;
        float w0 = 0.f, w1 = 0.f, w2 = 0.f, w3 = 0.f;
        if (lane < cnt) {
            s = g_csr[e0 + lane];
            float4 as = *(const float4*)&g_as1[s * 4];
            w0 = __expf(lrelu(as.x + ad.x));
            w1 = __expf(lrelu(as.y + ad.y));
            w2 = __expf(lrelu(as.z + ad.z));
            w3 = __expf(lrelu(as.w + ad.w));
            d0 += w0; d1 += w1; d2 += w2; d3 += w3;
        }
        int j = 0;
        for (; j + 4 <= cnt; j += 4) {
            int sj[4];
            float uq[4];
            uint2 rv[4];
#pragma unroll
            for (int q = 0; q < 4; q++) {
                int ln = j + q;
                sj[q] = __shfl_sync(0xffffffffu, s, ln);
                float u0 = __shfl_sync(0xffffffffu, w0, ln);
                float u1 = __shfl_sync(0xffffffffu, w1, ln);
                float u2 = __shfl_sync(0xffffffffu, w2, ln);
                float u3 = __shfl_sync(0xffffffffu, w3, ln);
                uq[q] = (hsel < 2) ? (hsel == 0 ? u0 : u1) : (hsel == 2 ? u2 : u3);
            }
#pragma unroll
            for (int q = 0; q < 4; q++)
                rv[q] = *(const uint2*)&h[(size_t)sj[q] * 128 + lane * 4];
#pragma unroll
            for (int q = 0; q < 4; q++) {
                float2 va = unpack_bf2(rv[q].x);
                float2 vb = unpack_bf2(rv[q].y);
                acc.x += uq[q] * va.x;
                acc.y += uq[q] * va.y;
                acc.z += uq[q] * vb.x;
                acc.w += uq[q] * vb.y;
            }
        }
        for (; j < cnt; j++) {
            int sj = __shfl_sync(0xffffffffu, s, j);
            float u0 = __shfl_sync(0xffffffffu, w0, j);
            float u1 = __shfl_sync(0xffffffffu, w1, j);
            float u2 = __shfl_sync(0xffffffffu, w2, j);
            float u3 = __shfl_sync(0xffffffffu, w3, j);
            float uq = (hsel < 2) ? (hsel == 0 ? u0 : u1) : (hsel == 2 ? u2 : u3);
            uint2 rv = *(const uint2*)&h[(size_t)sj * 128 + lane * 4];
            float2 va = unpack_bf2(rv.x);
            float2 vb = unpack_bf2(rv.y);
            acc.x += uq * va.x;
            acc.y += uq * va.y;
            acc.z += uq * vb.x;
            acc.w += uq * vb.y;
        }
    }
#pragma unroll
    for (int off = 16; off > 0; off >>= 1) {
        d0 += __shfl_xor_sync(0xffffffffu, d0, off);
        d1 += __shfl_xor_sync(0xffffffffu, d1, off);
        d2 += __shfl_xor_sync(0xffffffffu, d2, off);
        d3 += __shfl_xor_sync(0xffffffffu, d3, off);
    }
    float dsel = (hsel < 2) ? (hsel == 0 ? d0 : d1) : (hsel == 2 ? d2 : d3);
    float r = 1.f / (dsel + EPSV);
    float4 bv = *(const float4*)&b[lane * 4];
    float4 o;
    o.x = sigm(acc.x * r + bv.x);
    o.y = sigm(acc.y * r + bv.y);
    o.z = sigm(acc.z * r + bv.z);
    o.w = sigm(acc.w * r + bv.w);
    *(float4*)&out[(size_t)n * 128 + lane * 4] = o;
}

// ---------------- layer-2 aggregation: bf16 gather (uint32 per edge per lane) ----------------
__global__ void k_agg2(const uint16_t* __restrict__ h, const float* __restrict__ b,
                       float* __restrict__ out) {
    int n = (blockIdx.x * blockDim.x + threadIdx.x) >> 5;
    int lane = threadIdx.x & 31;
    if (n >= NN) return;
    int beg = g_off[n], end = g_off[n + 1];
    float ad = g_ad2[n];

    float2 acc = make_float2(0.f, 0.f);
    float d = 0.f;
    for (int e0 = beg; e0 < end; e0 += 32) {
        int cnt = min(32, end - e0);
        int s = 0;
        float w = 0.f;
        if (lane < cnt) {
            s = g_csr[e0 + lane];
            w = __expf(lrelu(g_as2[s] + ad));
            d += w;
        }
        int j = 0;
        for (; j + 4 <= cnt; j += 4) {
            int sj[4];
            float u[4];
            uint32_t rv[4];
#pragma unroll
            for (int q = 0; q < 4; q++) {
                sj[q] = __shfl_sync(0xffffffffu, s, j + q);
                u[q] = __shfl_sync(0xffffffffu, w, j + q);
            }
#pragma unroll
            for (int q = 0; q < 4; q++)
                rv[q] = *(const uint32_t*)&h[(size_t)sj[q] * 64 + lane * 2];
#pragma unroll
            for (int q = 0; q < 4; q++) {
                float2 v = unpack_bf2(rv[q]);
                acc.x += u[q] * v.x;
                acc.y += u[q] * v.y;
            }
        }
        for (; j < cnt; j++) {
            int sj = __shfl_sync(0xffffffffu, s, j);
            float u = __shfl_sync(0xffffffffu, w, j);
            float2 v = unpack_bf2(*(const uint32_t*)&h[(size_t)sj * 64 + lane * 2]);
            acc.x += u * v.x;
            acc.y += u * v.y;
        }
    }
#pragma unroll
    for (int off = 16; off > 0; off >>= 1)
        d += __shfl_xor_sync(0xffffffffu, d, off);
    float r = 1.f / (d + EPSV);
    float2 bv = *(const float2*)&b[lane * 2];
    float2 o;
    o.x = sigm(acc.x * r + bv.x);
    o.y = sigm(acc.y * r + bv.y);
    *(float2*)&out[(size_t)n * 64 + lane * 2] = o;
}

// ---------------- launch: fork preprocessing onto a side stream ----------------
extern "C" void kernel_launch(void* const* d_in, const int* in_sizes, int n_in,
                              void* d_out, int out_size) {
    const float* x     = (const float*)d_in[0];
    const void*  ei    = d_in[1];
    const float* W1    = (const float*)d_in[2];
    const float* at_s1 = (const float*)d_in[3];
    const float* at_d1 = (const float*)d_in[4];
    const float* b1    = (const float*)d_in[5];
    const float* W2    = (const float*)d_in[6];
    const float* at_s2 = (const float*)d_in[7];
    const float* at_d2 = (const float*)d_in[8];
    const float* b2    = (const float*)d_in[9];
    float* out = (float*)d_out;

    uint16_t *h1p, *h2p;
    float *out1p, *as1p, *ad1p, *as2p, *ad2p;
    cudaGetSymbolAddress((void**)&h1p, g_h1);
    cudaGetSymbolAddress((void**)&out1p, g_out1);
    cudaGetSymbolAddress((void**)&h2p, g_h2);
    cudaGetSymbolAddress((void**)&as1p, g_as1);
    cudaGetSymbolAddress((void**)&ad1p, g_ad1);
    cudaGetSymbolAddress((void**)&as2p, g_as2);
    cudaGetSymbolAddress((void**)&ad2p, g_ad2);

    const int SM1 = 4 * 128 * 72 * 2 / 2 * 2 + 2 * 32 * 136 * 4 + 2 * 128 * 4;  // 72704
    const int SM2 = 2 * 128 * 72 * 2 + 2 * 32 * 72 * 4 + 2 * 64 * 4;            // 55808
    cudaFuncSetAttribute(k_mma<128, 4, 32>, cudaFuncAttributeMaxDynamicSharedMemorySize, SM1);
    cudaFuncSetAttribute(k_mma<64, 1, 64>, cudaFuncAttributeMaxDynamicSharedMemorySize, SM2);

    static cudaStream_t s2 = nullptr;
    static cudaEvent_t evF = nullptr, evJ = nullptr;
    if (!s2) {
        cudaStreamCreateWithFlags(&s2, cudaStreamNonBlocking);
        cudaEventCreateWithFlags(&evF, cudaEventDisableTiming);
        cudaEventCreateWithFlags(&evJ, cudaEventDisableTiming);
    }

    // fork: preprocessing on s2, concurrent with mma1 on main
    cudaEventRecord(evF, 0);
    cudaStreamWaitEvent(s2, evF, 0);

    k_detect<<<1, 32, 0, s2>>>((const unsigned int*)ei);
    k_degree<<<EE / 1024, 256, 0, s2>>>(ei);
    k_scanA<<<64, 1024, 0, s2>>>();
    k_scanB<<<64, 1024, 0, s2>>>();
    k_csr<<<EE / 1024, 256, 0, s2>>>(ei);
    cudaEventRecord(evJ, s2);

    k_mma<128, 4, 32><<<NN / 128, 256, SM1>>>(x, W1, at_s1, at_d1, h1p, as1p, ad1p);

    // join
    cudaStreamWaitEvent(0, evJ, 0);
    k_agg1<<<NN / 8, 256>>>(h1p, b1, out1p);
    k_mma<64, 1, 64><<<NN / 128, 256, SM2>>>(out1p, W2, at_s2, at_d2, h2p, as2p, ad2p);
    k_agg2<<<NN / 8, 256>>>(h2p, b2, out);
}